// round 11
// baseline (speedup 1.0000x reference)
#include <cuda_runtime.h>
#include <cuda_fp16.h>
#include <cuda_bf16.h>

// Problem constants (fixed by the dataset)
#define Bc   4
#define Cc   16
#define Hc   256
#define Wc   256
#define HWc  (Hc * Wc)
#define Coc  16
#define Kc   9
#define INV_N (1.0f / (float)(Bc * Coc * HWc))

// Tiling: 32x16 pixel tile, 256 threads, 2 pixels/thread (rows r, r+8)
#define TILE_W 32
#define TILE_H 16
#define PAD    6
#define ROWS   (TILE_H + 2 * PAD)     // 28
#define COLS   (TILE_W + 2 * PAD)     // 44
#define NSITES (ROWS * COLS)          // 1232
#define SITE_U4 3                     // 48B per site: 16 fp16 ch + 8 pad halves
#define SIN_BYTES   (NSITES * SITE_U4 * 16)         // 59136
#define SKER_H2     (Kc * Cc * Coc / 2)             // 1152 half2
#define SMEM_BYTES  (SIN_BYTES + SKER_H2 * 4)       // 63744 B -> 3 blocks/SM

#define NPX 2

__global__ void zero_out_kernel(float* out) {
    if (threadIdx.x == 0) out[0] = 0.0f;
}

extern __shared__ char smemc[];

__global__ __launch_bounds__(256, 3) void dcn_loss_kernel(
    const float* __restrict__ offsets,  // [B, 18, H, W]
    const float* __restrict__ input,    // [B, 16, H, W]
    const float* __restrict__ ker,      // [16, 16, 3, 3]
    const float* __restrict__ target,   // [B, 16, H, W]
    float* __restrict__ out)
{
    const int tid = threadIdx.x;
    const int b   = blockIdx.z;
    const int rowBase = blockIdx.y * TILE_H;
    const int colBase = blockIdx.x * TILE_W;
    const int rowLo = rowBase - PAD;
    const int colLo = colBase - PAD;

    const float* inB = input + b * Cc * HWc;
    uint4*   sIn  = (uint4*)smemc;                        // 3 uint4 per site (48B)
    __half2* skwh = (__half2*)(smemc + SIN_BYTES);        // packed half2 weights

    // ---- Stage input tile as fp16, site-major, 48B stride (zeros outside) ----
    for (int i = tid; i < NSITES; i += 256) {
        const int ry = i / COLS;
        const int rx = i - ry * COLS;
        const int gy = rowLo + ry;
        const int gx = colLo + rx;
        const bool ok = ((unsigned)gy < Hc) && ((unsigned)gx < Wc);
        const float* src = inB + gy * Wc + gx;
        __half2 h[8];
        #pragma unroll
        for (int j = 0; j < 8; j++) {
            float v0 = ok ? __ldg(src + (2 * j) * HWc)     : 0.0f;
            float v1 = ok ? __ldg(src + (2 * j + 1) * HWc) : 0.0f;
            h[j] = __floats2half2_rn(v0, v1);
        }
        sIn[SITE_U4 * i]     = *(const uint4*)&h[0];
        sIn[SITE_U4 * i + 1] = *(const uint4*)&h[4];
        // third 16B chunk is padding, never read
    }

    // ---- Stage weights: skwh[(kk*16 + c)*8 + j] = (w[o=2j], w[o=2j+1]) ----
    for (int i = tid; i < SKER_H2; i += 256) {
        const int j  = i & 7;           // output pair
        const int ck = i >> 3;          // kk*16 + c
        const int kk = ck >> 4;
        const int c  = ck & 15;
        const float w0 = ker[(2 * j)     * (Cc * Kc) + c * Kc + kk];
        const float w1 = ker[(2 * j + 1) * (Cc * Kc) + c * Kc + kk];
        skwh[i] = __floats2half2_rn(w0, w1);
    }
    __syncthreads();

    // ---- Two pixels per thread ----
    const int lane = tid & 31;
    const int r    = tid >> 5;
    const int wpx  = colBase + lane;

    int hpx[NPX], hw[NPX];
    #pragma unroll
    for (int p = 0; p < NPX; p++) {
        hpx[p] = rowBase + r + 8 * p;
        hw[p]  = hpx[p] * Wc + wpx;
    }
    const float* offBase = offsets + b * 2 * Kc * HWc;
    const float* tgtBase = target  + b * Coc * HWc;

    __half2 acc[NPX][8];                 // acc[p][j] holds outputs (2j, 2j+1)
    #pragma unroll
    for (int p = 0; p < NPX; p++)
        #pragma unroll
        for (int j = 0; j < 8; j++)
            acc[p][j] = __float2half2_rn(0.0f);

    // Accumulate one channel's replicated sample against its 8 weight-half2
    auto acc_channel = [&](__half2* a, __half2 srep, const uint4 k0, const uint4 k1) {
        const __half2* ka = (const __half2*)&k0;
        const __half2* kb = (const __half2*)&k1;
        a[0] = __hfma2(srep, ka[0], a[0]);
        a[1] = __hfma2(srep, ka[1], a[1]);
        a[2] = __hfma2(srep, ka[2], a[2]);
        a[3] = __hfma2(srep, ka[3], a[3]);
        a[4] = __hfma2(srep, kb[0], a[4]);
        a[5] = __hfma2(srep, kb[1], a[5]);
        a[6] = __hfma2(srep, kb[2], a[6]);
        a[7] = __hfma2(srep, kb[3], a[7]);
    };

    // Fast path: sample one chunk (8 channels), accumulate immediately.
    auto do_pixel_fast = [&](int site, float wy, float wx, __half2* a, const uint4* kwb) {
        const __half2 h00 = __float2half2_rn((1.0f - wy) * (1.0f - wx));
        const __half2 h01 = __float2half2_rn((1.0f - wy) * wx);
        const __half2 h10 = __float2half2_rn(wy * (1.0f - wx));
        const __half2 h11 = __float2half2_rn(wy * wx);
        const uint4* p = sIn + SITE_U4 * site;
        #pragma unroll
        for (int chunk = 0; chunk < 2; chunk++) {
            const uint4 a00 = p[chunk];
            const uint4 a01 = p[SITE_U4 + chunk];
            const uint4 a10 = p[SITE_U4 * COLS + chunk];
            const uint4 a11 = p[SITE_U4 * COLS + SITE_U4 + chunk];
            const __half2* c00 = (const __half2*)&a00;
            const __half2* c01 = (const __half2*)&a01;
            const __half2* c10 = (const __half2*)&a10;
            const __half2* c11 = (const __half2*)&a11;
            #pragma unroll
            for (int j = 0; j < 4; j++) {
                __half2 v = __hmul2(c00[j], h00);
                v = __hfma2(c01[j], h01, v);
                v = __hfma2(c10[j], h10, v);
                v = __hfma2(c11[j], h11, v);
                const int cj = chunk * 4 + j;    // channel pair (2cj, 2cj+1)
                acc_channel(a, __low2half2(v),  kwb[4 * cj],     kwb[4 * cj + 1]);
                acc_channel(a, __high2half2(v), kwb[4 * cj + 2], kwb[4 * cj + 3]);
            }
        }
    };

    // Rare exact fallback from global (validity-masked, clamped idx)
    auto tap_generic = [&](float y, float x, __half2* a, const uint4* kwb) {
        const float y0f = floorf(y), x0f = floorf(x);
        const float wy = y - y0f, wx = x - x0f;
        const int y0 = (int)y0f, x0 = (int)x0f;
        const int y1 = y0 + 1, x1 = x0 + 1;
        const bool vy0 = ((unsigned)y0 < Hc), vy1 = ((unsigned)y1 < Hc);
        const bool vx0 = ((unsigned)x0 < Wc), vx1 = ((unsigned)x1 < Wc);
        const float w00 = (1.0f - wy) * (1.0f - wx) * (float)(vy0 && vx0);
        const float w01 = (1.0f - wy) * wx          * (float)(vy0 && vx1);
        const float w10 = wy          * (1.0f - wx) * (float)(vy1 && vx0);
        const float w11 = wy          * wx          * (float)(vy1 && vx1);
        const int cy0 = min(max(y0, 0), Hc - 1), cy1 = min(max(y1, 0), Hc - 1);
        const int cx0 = min(max(x0, 0), Wc - 1), cx1 = min(max(x1, 0), Wc - 1);
        const int i00 = cy0 * Wc + cx0, i01 = cy0 * Wc + cx1;
        const int i10 = cy1 * Wc + cx0, i11 = cy1 * Wc + cx1;
        #pragma unroll
        for (int c = 0; c < Cc; c++) {
            const float* ic = inB + c * HWc;
            const float s = w00 * __ldg(ic + i00) + w01 * __ldg(ic + i01)
                          + w10 * __ldg(ic + i10) + w11 * __ldg(ic + i11);
            acc_channel(a, __float2half2_rn(s), kwb[2 * c], kwb[2 * c + 1]);
        }
    };

    // ---- kk loop with offset double-buffer prefetch ----
    float dy[NPX], dx[NPX];
    #pragma unroll
    for (int p = 0; p < NPX; p++) {
        dy[p] = __ldg(offBase + hw[p]);              // kk=0, y plane
        dx[p] = __ldg(offBase + HWc + hw[p]);        // kk=0, x plane
    }

    for (int kk = 0; kk < Kc; kk++) {
        float ndy[NPX], ndx[NPX];
        if (kk + 1 < Kc) {
            #pragma unroll
            for (int p = 0; p < NPX; p++) {
                ndy[p] = __ldg(offBase + (2 * kk + 2) * HWc + hw[p]);
                ndx[p] = __ldg(offBase + (2 * kk + 3) * HWc + hw[p]);
            }
        }

        const int kr = kk / 3;
        const int kc = kk - 3 * kr;
        const uint4* kwb = (const uint4*)(skwh + (kk * Cc) * 8);

        #pragma unroll
        for (int p = 0; p < NPX; p++) {
            const float y = dy[p] + (float)(hpx[p] - 1 + kr);
            const float x = dx[p] + (float)(wpx - 1 + kc);
            const float y0f = floorf(y), x0f = floorf(x);
            const int ry0 = (int)y0f - rowLo;
            const int rx0 = (int)x0f - colLo;
            if (((unsigned)ry0 <= (ROWS - 2)) && ((unsigned)rx0 <= (COLS - 2)))
                do_pixel_fast(ry0 * COLS + rx0, y - y0f, x - x0f, acc[p], kwb);
            else
                tap_generic(y, x, acc[p], kwb);
        }

        #pragma unroll
        for (int p = 0; p < NPX; p++) { dy[p] = ndy[p]; dx[p] = ndx[p]; }
    }

    // ---- Squared error vs target (fp32) ----
    float local = 0.0f;
    #pragma unroll
    for (int p = 0; p < NPX; p++) {
        const float* tg = tgtBase + hw[p];
        #pragma unroll
        for (int j = 0; j < 8; j++) {
            const float2 f2 = __half22float2(acc[p][j]);
            const float d0 = f2.x - __ldg(tg + (2 * j) * HWc);
            const float d1 = f2.y - __ldg(tg + (2 * j + 1) * HWc);
            local += d0 * d0 + d1 * d1;
        }
    }

    // ---- Warp + block reduce, one atomic per block ----
    #pragma unroll
    for (int s = 16; s > 0; s >>= 1)
        local += __shfl_xor_sync(0xFFFFFFFFu, local, s);

    __shared__ float red[8];
    if ((tid & 31) == 0) red[tid >> 5] = local;
    __syncthreads();
    if (tid < 8) {
        float v = red[tid];
        #pragma unroll
        for (int s = 4; s > 0; s >>= 1)
            v += __shfl_xor_sync(0xFFu, v, s);
        if (tid == 0) atomicAdd(out, v * INV_N);
    }
}

extern "C" void kernel_launch(void* const* d_in, const int* in_sizes, int n_in,
                              void* d_out, int out_size) {
    const float* offsets = (const float*)d_in[0];
    const float* input   = (const float*)d_in[1];
    const float* ker     = (const float*)d_in[2];
    const float* target  = (const float*)d_in[3];
    float* out = (float*)d_out;

    static bool attr_set = false;
    if (!attr_set) {
        cudaFuncSetAttribute(dcn_loss_kernel,
                             cudaFuncAttributeMaxDynamicSharedMemorySize,
                             SMEM_BYTES);
        attr_set = true;
    }

    zero_out_kernel<<<1, 32>>>(out);

    dim3 grid(Wc / TILE_W, Hc / TILE_H, Bc);   // 8 x 16 x 4 = 512 blocks
    dcn_loss_kernel<<<grid, 256, SMEM_BYTES>>>(offsets, input, ker, target, out);
}

// round 14
// speedup vs baseline: 4.1047x; 4.1047x over previous
#include <cuda_runtime.h>
#include <cuda_fp16.h>
#include <cuda_bf16.h>

// Problem constants (fixed by the dataset)
#define Bc   4
#define Cc   16
#define Hc   256
#define Wc   256
#define HWc  (Hc * Wc)
#define Coc  16
#define Kc   9
#define INV_N (1.0f / (float)(Bc * Coc * HWc))

// Tiling: 32x32 pixel tile, 256 threads, 4 pixels/thread (rows r+0,8,16,24)
#define TILE_W 32
#define TILE_H 32
#define PAD    6
#define ROWS   (TILE_H + 2 * PAD)     // 44
#define COLS   (TILE_W + 2 * PAD)     // 44
#define NSITES (ROWS * COLS)          // 1936
#define SITE_U4 3                     // 48B per site: 16 fp16 ch + 8 pad halves
#define SIN_BYTES   (NSITES * SITE_U4 * 16)         // 92928
#define SKER_H2     (Kc * Cc * Coc / 2)             // 1152 half2
#define SMEM_BYTES  (SIN_BYTES + SKER_H2 * 4)       // 97536 B

#define NPX 4

__global__ void zero_out_kernel(float* out) {
    if (threadIdx.x == 0) out[0] = 0.0f;
}

extern __shared__ char smemc[];

__global__ __launch_bounds__(256, 2) void dcn_loss_kernel(
    const float* __restrict__ offsets,  // [B, 18, H, W]
    const float* __restrict__ input,    // [B, 16, H, W]
    const float* __restrict__ ker,      // [16, 16, 3, 3]
    const float* __restrict__ target,   // [B, 16, H, W]
    float* __restrict__ out)
{
    const int tid = threadIdx.x;
    const int b   = blockIdx.z;
    const int rowBase = blockIdx.y * TILE_H;
    const int colBase = blockIdx.x * TILE_W;
    const int rowLo = rowBase - PAD;
    const int colLo = colBase - PAD;

    const float* inB = input + b * Cc * HWc;
    uint4*   sIn  = (uint4*)smemc;                     // 3 uint4 per site (48B)
    __half2* skwh = (__half2*)(smemc + SIN_BYTES);     // packed half2 weights

    // ---- Stage input tile as fp16, site-major, 48B stride (zeros outside) ----
    for (int i = tid; i < NSITES; i += 256) {
        const int ry = i / COLS;
        const int rx = i - ry * COLS;
        const int gy = rowLo + ry;
        const int gx = colLo + rx;
        const bool ok = ((unsigned)gy < Hc) && ((unsigned)gx < Wc);
        const float* src = inB + gy * Wc + gx;
        __half2 h[8];
        #pragma unroll
        for (int j = 0; j < 8; j++) {
            float v0 = ok ? __ldg(src + (2 * j) * HWc)     : 0.0f;
            float v1 = ok ? __ldg(src + (2 * j + 1) * HWc) : 0.0f;
            h[j] = __floats2half2_rn(v0, v1);
        }
        sIn[SITE_U4 * i]     = *(const uint4*)&h[0];
        sIn[SITE_U4 * i + 1] = *(const uint4*)&h[4];
        // third 16B chunk is padding, never read
    }

    // ---- Stage weights: skwh[(kk*16 + c)*8 + j] = (w[o=2j], w[o=2j+1]) ----
    for (int i = tid; i < SKER_H2; i += 256) {
        const int j  = i & 7;           // output pair
        const int ck = i >> 3;          // kk*16 + c
        const int kk = ck >> 4;
        const int c  = ck & 15;
        const float w0 = ker[(2 * j)     * (Cc * Kc) + c * Kc + kk];
        const float w1 = ker[(2 * j + 1) * (Cc * Kc) + c * Kc + kk];
        skwh[i] = __floats2half2_rn(w0, w1);
    }
    __syncthreads();

    // ---- Four pixels per thread ----
    const int lane = tid & 31;
    const int r    = tid >> 5;
    const int wpx  = colBase + lane;

    int   hpx[NPX], hw[NPX];
    #pragma unroll
    for (int p = 0; p < NPX; p++) {
        hpx[p] = rowBase + r + 8 * p;
        hw[p]  = hpx[p] * Wc + wpx;
    }
    const float* offBase = offsets + b * 2 * Kc * HWc;
    const float* tgtBase = target  + b * Coc * HWc;

    __half2 acc[NPX][8];                 // acc[p][j] holds outputs (2j, 2j+1)
    #pragma unroll
    for (int p = 0; p < NPX; p++)
        #pragma unroll
        for (int j = 0; j < 8; j++)
            acc[p][j] = __float2half2_rn(0.0f);

    // Accumulate one channel's replicated sample against its 8 weight-half2
    auto acc_channel = [&](__half2* a, __half2 srep, const uint4 k0, const uint4 k1) {
        const __half2* ka = (const __half2*)&k0;
        const __half2* kb = (const __half2*)&k1;
        a[0] = __hfma2(srep, ka[0], a[0]);
        a[1] = __hfma2(srep, ka[1], a[1]);
        a[2] = __hfma2(srep, ka[2], a[2]);
        a[3] = __hfma2(srep, ka[3], a[3]);
        a[4] = __hfma2(srep, kb[0], a[4]);
        a[5] = __hfma2(srep, kb[1], a[5]);
        a[6] = __hfma2(srep, kb[2], a[6]);
        a[7] = __hfma2(srep, kb[3], a[7]);
    };

    // Rare exact fallback from global (validity-masked, clamped idx)
    auto tap_generic = [&](float y, float x, __half2* a, int kk) {
        const float y0f = floorf(y), x0f = floorf(x);
        const float wy = y - y0f, wx = x - x0f;
        const int y0 = (int)y0f, x0 = (int)x0f;
        const int y1 = y0 + 1, x1 = x0 + 1;
        const bool vy0 = ((unsigned)y0 < Hc), vy1 = ((unsigned)y1 < Hc);
        const bool vx0 = ((unsigned)x0 < Wc), vx1 = ((unsigned)x1 < Wc);
        const float w00 = (1.0f - wy) * (1.0f - wx) * (float)(vy0 && vx0);
        const float w01 = (1.0f - wy) * wx          * (float)(vy0 && vx1);
        const float w10 = wy          * (1.0f - wx) * (float)(vy1 && vx0);
        const float w11 = wy          * wx          * (float)(vy1 && vx1);
        const int cy0 = min(max(y0, 0), Hc - 1), cy1 = min(max(y1, 0), Hc - 1);
        const int cx0 = min(max(x0, 0), Wc - 1), cx1 = min(max(x1, 0), Wc - 1);
        const int i00 = cy0 * Wc + cx0, i01 = cy0 * Wc + cx1;
        const int i10 = cy1 * Wc + cx0, i11 = cy1 * Wc + cx1;
        const uint4* kwb = (const uint4*)(skwh + (kk * Cc) * 8);
        #pragma unroll
        for (int c = 0; c < Cc; c++) {
            const float* ic = inB + c * HWc;
            const float s = w00 * __ldg(ic + i00) + w01 * __ldg(ic + i01)
                          + w10 * __ldg(ic + i10) + w11 * __ldg(ic + i11);
            acc_channel(a, __float2half2_rn(s), kwb[2 * c], kwb[2 * c + 1]);
        }
    };

    // ---- kk loop with offset prefetch ----
    float dy[NPX], dx[NPX];
    #pragma unroll
    for (int p = 0; p < NPX; p++) {
        dy[p] = __ldg(offBase + hw[p]);              // kk=0, y plane
        dx[p] = __ldg(offBase + HWc + hw[p]);        // kk=0, x plane
    }

    for (int kk = 0; kk < Kc; kk++) {
        float ndy[NPX], ndx[NPX];
        if (kk + 1 < Kc) {
            #pragma unroll
            for (int p = 0; p < NPX; p++) {
                ndy[p] = __ldg(offBase + (2 * kk + 2) * HWc + hw[p]);
                ndx[p] = __ldg(offBase + (2 * kk + 3) * HWc + hw[p]);
            }
        }

        const int kr = kk / 3;
        const int kc = kk - 3 * kr;

        float wyv[NPX], wxv[NPX];
        int   sitev[NPX];
        bool  allfast = true;
        float yv[NPX], xv[NPX];
        #pragma unroll
        for (int p = 0; p < NPX; p++) {
            yv[p] = dy[p] + (float)(hpx[p] - 1 + kr);
            xv[p] = dx[p] + (float)(wpx - 1 + kc);
            const float y0f = floorf(yv[p]);
            const float x0f = floorf(xv[p]);
            wyv[p] = yv[p] - y0f;
            wxv[p] = xv[p] - x0f;
            const int ry0 = (int)y0f - rowLo;
            const int rx0 = (int)x0f - colLo;
            sitev[p] = ry0 * COLS + rx0;
            allfast &= ((unsigned)ry0 <= (ROWS - 2)) && ((unsigned)rx0 <= (COLS - 2));
        }

        if (allfast) {
            const uint4* kwb = (const uint4*)(skwh + (kk * Cc) * 8);

            // Chunk-wise: channels 0-7 then 8-15 (halves live sample registers)
            #pragma unroll
            for (int chunk = 0; chunk < 2; chunk++) {
                __half2 sv[NPX][4];
                #pragma unroll
                for (int p = 0; p < NPX; p++) {
                    const __half2 h00 = __float2half2_rn((1.0f - wyv[p]) * (1.0f - wxv[p]));
                    const __half2 h01 = __float2half2_rn((1.0f - wyv[p]) * wxv[p]);
                    const __half2 h10 = __float2half2_rn(wyv[p] * (1.0f - wxv[p]));
                    const __half2 h11 = __float2half2_rn(wyv[p] * wxv[p]);
                    const uint4* sp = sIn + SITE_U4 * sitev[p];
                    const uint4 a00 = sp[chunk];
                    const uint4 a01 = sp[SITE_U4 + chunk];
                    const uint4 a10 = sp[SITE_U4 * COLS + chunk];
                    const uint4 a11 = sp[SITE_U4 * COLS + SITE_U4 + chunk];
                    const __half2* c00 = (const __half2*)&a00;
                    const __half2* c01 = (const __half2*)&a01;
                    const __half2* c10 = (const __half2*)&a10;
                    const __half2* c11 = (const __half2*)&a11;
                    #pragma unroll
                    for (int j = 0; j < 4; j++) {
                        __half2 v = __hmul2(c00[j], h00);
                        v = __hfma2(c01[j], h01, v);
                        v = __hfma2(c10[j], h10, v);
                        v = __hfma2(c11[j], h11, v);
                        sv[p][j] = v;
                    }
                }

                #pragma unroll
                for (int j = 0; j < 4; j++) {
                    const int cj = chunk * 4 + j;        // channel pair (2cj, 2cj+1)
                    const uint4 kA0 = kwb[(2 * cj) * 2];
                    const uint4 kA1 = kwb[(2 * cj) * 2 + 1];
                    const uint4 kB0 = kwb[(2 * cj + 1) * 2];
                    const uint4 kB1 = kwb[(2 * cj + 1) * 2 + 1];
                    #pragma unroll
                    for (int p = 0; p < NPX; p++) {
                        acc_channel(acc[p], __low2half2(sv[p][j]),  kA0, kA1);
                        acc_channel(acc[p], __high2half2(sv[p][j]), kB0, kB1);
                    }
                }
            }
        } else {
            #pragma unroll
            for (int p = 0; p < NPX; p++)
                tap_generic(yv[p], xv[p], acc[p], kk);
        }

        #pragma unroll
        for (int p = 0; p < NPX; p++) { dy[p] = ndy[p]; dx[p] = ndx[p]; }
    }

    // ---- Squared error vs target (fp32) ----
    float local = 0.0f;
    #pragma unroll
    for (int p = 0; p < NPX; p++) {
        const float* tg = tgtBase + hw[p];
        #pragma unroll
        for (int j = 0; j < 8; j++) {
            const float2 f2 = __half22float2(acc[p][j]);
            const float d0 = f2.x - __ldg(tg + (2 * j) * HWc);
            const float d1 = f2.y - __ldg(tg + (2 * j + 1) * HWc);
            local += d0 * d0 + d1 * d1;
        }
    }

    // ---- Warp + block reduce, one atomic per block ----
    #pragma unroll
    for (int s = 16; s > 0; s >>= 1)
        local += __shfl_xor_sync(0xFFFFFFFFu, local, s);

    __shared__ float red[8];
    if ((tid & 31) == 0) red[tid >> 5] = local;
    __syncthreads();
    if (tid < 8) {
        float v = red[tid];
        #pragma unroll
        for (int s = 4; s > 0; s >>= 1)
            v += __shfl_xor_sync(0xFFu, v, s);
        if (tid == 0) atomicAdd(out, v * INV_N);
    }
}

extern "C" void kernel_launch(void* const* d_in, const int* in_sizes, int n_in,
                              void* d_out, int out_size) {
    const float* offsets = (const float*)d_in[0];
    const float* input   = (const float*)d_in[1];
    const float* ker     = (const float*)d_in[2];
    const float* target  = (const float*)d_in[3];
    float* out = (float*)d_out;

    static bool attr_set = false;
    if (!attr_set) {
        cudaFuncSetAttribute(dcn_loss_kernel,
                             cudaFuncAttributeMaxDynamicSharedMemorySize,
                             SMEM_BYTES);
        attr_set = true;
    }

    zero_out_kernel<<<1, 32>>>(out);

    dim3 grid(Wc / TILE_W, Hc / TILE_H, Bc);   // 8 x 8 x 4 = 256 blocks
    dcn_loss_kernel<<<grid, 256, SMEM_BYTES>>>(offsets, input, ker, target, out);
}